// round 1
// baseline (speedup 1.0000x reference)
#include <cuda_runtime.h>

// Problem constants (fixed by the reference setup)
#define WSZ   7
#define W     15            // 2*w+1
#define WW    225           // W*W
#define NC    8             // channels
#define CWW   1800          // NC*W*W floats per (b,p) output row
#define NF4   450           // CWW / 4 float4 per row
#define LSEQ  4096
#define PLEN  (LSEQ - 2*WSZ)   // 4082
#define NB    16

__global__ __launch_bounds__(256, 8)
void local_interactions_kernel(const float* __restrict__ in, float* __restrict__ out)
{
    __shared__ float s_top[NC][W];
    __shared__ float s_bot[NC][W];

    const int bp  = blockIdx.x;            // 0 .. NB*PLEN-1
    const int b   = bp / PLEN;
    const int p   = bp - b * PLEN;
    const int tid = threadIdx.x;

    // Load the 8 channel windows (top & bot interleaved in input last dim).
    // in layout: (B, C, L, 2) row-major.
    if (tid < NC * W) {
        const int c = tid / W;
        const int i = tid - c * W;
        const float* base = in + ((((size_t)(b * NC + c)) * LSEQ + (p + i)) << 1);
        s_top[c][i] = base[0];
        s_bot[c][i] = base[1];
    }
    __syncthreads();

    // Output row for this (b,p): 1800 contiguous floats, 16B aligned.
    float4* orow = reinterpret_cast<float4*>(out + (size_t)bp * CWW);

    // 450 float4 per row; 256 threads -> <=2 iterations each.
    for (int k = tid; k < NF4; k += 256) {
        const int e = k << 2;
        float4 v;
        float* vp = reinterpret_cast<float*>(&v);
        #pragma unroll
        for (int s = 0; s < 4; ++s) {
            const int ee  = e + s;
            const int c   = ee / WW;
            const int rem = ee - c * WW;
            const int i   = rem / W;
            const int j   = rem - i * W;
            vp[s] = s_top[c][i] * s_bot[c][j];
        }
        __stcs(&orow[k], v);   // streaming store: output >> L2, don't cache
    }
}

extern "C" void kernel_launch(void* const* d_in, const int* in_sizes, int n_in,
                              void* d_out, int out_size)
{
    const float* in  = (const float*)d_in[0];
    float*       out = (float*)d_out;
    const int grid = NB * PLEN;   // 65312 blocks
    local_interactions_kernel<<<grid, 256>>>(in, out);
}

// round 2
// speedup vs baseline: 1.3534x; 1.3534x over previous
#include <cuda_runtime.h>

// Problem constants (fixed by the reference setup)
#define WSZ   7
#define W     15             // 2*w+1
#define WW    225            // W*W
#define NC    8              // channels
#define CWW   1800           // NC*W*W floats per (b,p) output row
#define LSEQ  4096
#define PLEN  (LSEQ - 2*WSZ) // 4082
#define NB    16

#define ECHUNK   300         // elements per block (6 chunks * 300 = 1800)
#define NECHUNK  6
#define PP       128         // p values per block
#define NPCHUNK  ((PLEN + PP - 1) / PP)   // 32
#define NTHREADS 320
#define NWIN     (PP + 2*WSZ)             // 142 window columns staged

__global__ __launch_bounds__(NTHREADS)
void local_interactions_kernel(const float* __restrict__ in, float* __restrict__ out)
{
    // smem: rows 2c = top channel c, rows 2c+1 = bot channel c, NWIN columns
    __shared__ float s[2 * NC][NWIN];

    const int tid = threadIdx.x;
    const int ec  = blockIdx.x;          // element chunk  (0..5)
    const int pc  = blockIdx.y;          // p chunk        (0..31)
    const int b   = blockIdx.z;          // batch          (0..15)
    const int p0  = pc * PP;

    // ---- Stage the input window: 8 channels x NWIN cols of (top,bot) float2 ----
    const float2* in2 = reinterpret_cast<const float2*>(in);
    for (int t = tid; t < NC * NWIN; t += NTHREADS) {
        const int c   = t / NWIN;
        const int col = t - c * NWIN;
        const int gp  = p0 + col;
        if (gp < LSEQ) {
            float2 v = in2[(size_t)(b * NC + c) * LSEQ + gp];
            s[2 * c][col]     = v.x;   // top
            s[2 * c + 1][col] = v.y;   // bot
        }
    }
    __syncthreads();

    // ---- Each thread owns one fixed flat element e = (c,i,j); streams over p ----
    if (tid < ECHUNK) {
        const int e   = ec * ECHUNK + tid;     // 0..1799
        const int c   = e / WW;
        const int rem = e - c * WW;
        const int i   = rem / W;
        const int j   = rem - i * W;

        const float* tp = &s[2 * c][i];        // advances +1 per p
        const float* bt = &s[2 * c + 1][j];

        const int np = min(PP, PLEN - p0);
        float* op = out + (size_t)(b * PLEN + p0) * CWW + e;   // +CWW per p

        #pragma unroll 4
        for (int lp = 0; lp < np; ++lp) {
            __stcs(op, tp[lp] * bt[lp]);       // coalesced 128B/warp, streaming
            op += CWW;
        }
    }
}

extern "C" void kernel_launch(void* const* d_in, const int* in_sizes, int n_in,
                              void* d_out, int out_size)
{
    const float* in  = (const float*)d_in[0];
    float*       out = (float*)d_out;
    dim3 grid(NECHUNK, NPCHUNK, NB);
    local_interactions_kernel<<<grid, NTHREADS>>>(in, out);
}

// round 3
// speedup vs baseline: 1.5254x; 1.1271x over previous
#include <cuda_runtime.h>

#define WSZ   7
#define W     15
#define WW    225
#define NC    8
#define CWW   1800                   // floats per (b,p) output row
#define LSEQ  4096
#define PLEN  (LSEQ - 2*WSZ)         // 4082
#define NB    16

#define PP       16                  // p-values per block
#define NPCHUNK  ((PLEN + PP - 1) / PP)   // 256
#define NT       480                 // 450 compute-active (one quad each)
#define NQUAD    450                 // 1800/4 quads per row
#define NWIN     (PP + 2*WSZ)        // 30 staged columns
#define NWINP    32                  // padded

__global__ __launch_bounds__(NT)
void local_interactions_kernel(const float* __restrict__ in, float* __restrict__ out)
{
    // Phase-replicated windows: s[top/bot][c][ph][y] with copy_ph[y] = orig[y+ph]
    __shared__ float s[2][NC][2][NWINP];

    const int tid = threadIdx.x;
    const int pc  = blockIdx.x;                 // p-chunk
    const int b   = blockIdx.y;                 // batch
    const int p0  = pc * PP;
    const int np  = min(PP, PLEN - p0);

    // ---- Stage: 8 channels x NWIN (top,bot) pairs, written to both phase copies ----
    const float2* in2 = reinterpret_cast<const float2*>(in);
    for (int t = tid; t < NC * NWIN; t += NT) {
        const int c   = t / NWIN;
        const int col = t - c * NWIN;
        const int gp  = p0 + col;
        if (gp < LSEQ) {
            float2 v = in2[(size_t)(b * NC + c) * LSEQ + gp];
            s[0][c][0][col] = v.x;
            s[1][c][0][col] = v.y;
            if (col >= 1) {
                s[0][c][1][col - 1] = v.x;
                s[1][c][1][col - 1] = v.y;
            }
        }
    }
    __syncthreads();

    if (tid >= NQUAD) return;

    // ---- Thread owns quad e0..e0+3; precompute per-slot aligned float2 bases ----
    const int e0 = tid << 2;
    const float2* tp[4];
    const float2* bp[4];
    #pragma unroll
    for (int sidx = 0; sidx < 4; ++sidx) {
        const int e   = e0 + sidx;
        const int c   = e / WW;
        const int rem = e - c * WW;
        const int i   = rem / W;
        const int j   = rem - i * W;
        // value orig[i+lp] lives at copy (i&1), y = (i&~1)+lp  (lp even)
        tp[sidx] = reinterpret_cast<const float2*>(&s[0][c][i & 1][i & ~1]);
        bp[sidx] = reinterpret_cast<const float2*>(&s[1][c][j & 1][j & ~1]);
    }

    float* ob = out + (size_t)(b * PLEN + p0) * CWW + e0;

    if (np == PP) {
        #pragma unroll 2
        for (int n = 0; n < PP / 2; ++n) {
            float2 T0 = tp[0][n], T1 = tp[1][n], T2 = tp[2][n], T3 = tp[3][n];
            float2 B0 = bp[0][n], B1 = bp[1][n], B2 = bp[2][n], B3 = bp[3][n];
            float4 v0 = make_float4(T0.x * B0.x, T1.x * B1.x, T2.x * B2.x, T3.x * B3.x);
            float4 v1 = make_float4(T0.y * B0.y, T1.y * B1.y, T2.y * B2.y, T3.y * B3.y);
            __stcs(reinterpret_cast<float4*>(ob + (2 * n)     * CWW), v0);
            __stcs(reinterpret_cast<float4*>(ob + (2 * n + 1) * CWW), v1);
        }
    } else {
        for (int n = 0; n < (np + 1) / 2; ++n) {
            float2 T0 = tp[0][n], T1 = tp[1][n], T2 = tp[2][n], T3 = tp[3][n];
            float2 B0 = bp[0][n], B1 = bp[1][n], B2 = bp[2][n], B3 = bp[3][n];
            float4 v0 = make_float4(T0.x * B0.x, T1.x * B1.x, T2.x * B2.x, T3.x * B3.x);
            __stcs(reinterpret_cast<float4*>(ob + (2 * n) * CWW), v0);
            if (2 * n + 1 < np) {
                float4 v1 = make_float4(T0.y * B0.y, T1.y * B1.y, T2.y * B2.y, T3.y * B3.y);
                __stcs(reinterpret_cast<float4*>(ob + (2 * n + 1) * CWW), v1);
            }
        }
    }
}

extern "C" void kernel_launch(void* const* d_in, const int* in_sizes, int n_in,
                              void* d_out, int out_size)
{
    const float* in  = (const float*)d_in[0];
    float*       out = (float*)d_out;
    dim3 grid(NPCHUNK, NB);
    local_interactions_kernel<<<grid, NT>>>(in, out);
}

// round 4
// speedup vs baseline: 1.6785x; 1.1004x over previous
#include <cuda_runtime.h>

#define WSZ   7
#define W     15
#define WW    225
#define NC    8
#define CWW   1800                   // floats per (b,p) output row
#define LSEQ  4096
#define PLEN  (LSEQ - 2*WSZ)         // 4082
#define NB    16

#define PP       16                  // p-values per block
#define NPCHUNK  ((PLEN + PP - 1) / PP)   // 256
#define NT       480
#define NQUAD    450                 // 1800/4 quads per row
#define NWIN     (PP + 2*WSZ)        // 30 staged columns
#define NWINP    32                  // padded row (128B)

__global__ __launch_bounds__(NT, 3)
void local_interactions_kernel(const float* __restrict__ in, float* __restrict__ out)
{
    // s[top/bot][c][phase][col], phase copy: copy_ph[y] = orig[y+ph]
    __shared__ float s[2][NC][2][NWINP];

    const int tid = threadIdx.x;
    const int pc  = blockIdx.x;
    const int b   = blockIdx.y;
    // Overlap-clamp the final chunk: overlapped p's are written identical
    // values by two blocks -> deterministic, and no tail path needed.
    const int p0  = min(pc * PP, PLEN - PP);

    // ---- Stage: 8 channels x NWIN (top,bot) float2, into both phase copies ----
    const float2* in2 = reinterpret_cast<const float2*>(in);
    for (int t = tid; t < NC * NWIN; t += NT) {
        const int c   = t / NWIN;
        const int col = t - c * NWIN;
        float2 v = in2[(size_t)(b * NC + c) * LSEQ + (p0 + col)];
        s[0][c][0][col] = v.x;
        s[1][c][0][col] = v.y;
        if (col >= 1) {
            s[0][c][1][col - 1] = v.x;
            s[1][c][1][col - 1] = v.y;
        }
    }
    __syncthreads();

    if (tid >= NQUAD) return;

    // ---- Per-slot operand addresses as 32-bit byte offsets (not pointers) ----
    const int e0 = tid << 2;
    unsigned ot[4], ob[4];
    #pragma unroll
    for (int si = 0; si < 4; ++si) {
        const int e   = e0 + si;
        const int c   = e / WW;
        const int rem = e - c * WW;
        const int i   = rem / W;
        const int j   = rem - i * W;
        // byte offset of s[tb][c][ph][col]
        ot[si] = ((((0 * NC + c) * 2 + (i & 1)) * NWINP) + (i & ~1)) * 4u;
        ob[si] = ((((1 * NC + c) * 2 + (j & 1)) * NWINP) + (j & ~1)) * 4u;
    }

    const char* sb = reinterpret_cast<const char*>(s);
    float* op = out + (size_t)(b * PLEN + p0) * CWW + e0;

    #pragma unroll 2
    for (int n = 0; n < PP / 2; ++n) {
        const unsigned d = 8u * n;
        float2 T0 = *reinterpret_cast<const float2*>(sb + ot[0] + d);
        float2 T1 = *reinterpret_cast<const float2*>(sb + ot[1] + d);
        float2 T2 = *reinterpret_cast<const float2*>(sb + ot[2] + d);
        float2 T3 = *reinterpret_cast<const float2*>(sb + ot[3] + d);
        float2 B0 = *reinterpret_cast<const float2*>(sb + ob[0] + d);
        float2 B1 = *reinterpret_cast<const float2*>(sb + ob[1] + d);
        float2 B2 = *reinterpret_cast<const float2*>(sb + ob[2] + d);
        float2 B3 = *reinterpret_cast<const float2*>(sb + ob[3] + d);
        float4 v0 = make_float4(T0.x * B0.x, T1.x * B1.x, T2.x * B2.x, T3.x * B3.x);
        float4 v1 = make_float4(T0.y * B0.y, T1.y * B1.y, T2.y * B2.y, T3.y * B3.y);
        __stcs(reinterpret_cast<float4*>(op + (2 * n)     * CWW), v0);
        __stcs(reinterpret_cast<float4*>(op + (2 * n + 1) * CWW), v1);
    }
}

extern "C" void kernel_launch(void* const* d_in, const int* in_sizes, int n_in,
                              void* d_out, int out_size)
{
    const float* in  = (const float*)d_in[0];
    float*       out = (float*)d_out;
    dim3 grid(NPCHUNK, NB);
    local_interactions_kernel<<<grid, NT>>>(in, out);
}

// round 7
// speedup vs baseline: 1.9183x; 1.1429x over previous
#include <cuda_runtime.h>

#define WSZ   7
#define W     15
#define WW    225
#define NC    8
#define CWW   1800                   // floats per (b,p) output row
#define LSEQ  4096
#define PLEN  (LSEQ - 2*WSZ)         // 4082
#define NB    16

#define PP       16                  // p-values per block
#define NPCHUNK  ((PLEN + PP - 1) / PP)   // 256
#define NT       480
#define NQUAD    450                 // 1800/4 quads per row
#define NWIN     (PP + 2*WSZ)        // 30 staged window columns
#define TROW     32                  // top row pad (floats)
#define BROW     36                  // bot phase-row pad (floats)

__global__ __launch_bounds__(NT, 3)
void local_interactions_kernel(const float* __restrict__ in, float* __restrict__ out)
{
    // top: plain window. bot: 4 phase-shifted copies with left pad of 4:
    //   sbot[c][ph][m] = bot_orig[c][m + ph - 4]
    // For window index x (x >= -3): orig[x..x+3] is the aligned float4 at
    //   ph = (x+4)&3,  m0 = (x+4)&~3     (bias +4 keeps everything non-negative)
    __shared__ float stop[NC][TROW];
    __shared__ float sbot[NC][4][BROW];

    const int tid = threadIdx.x;
    const int pc  = blockIdx.x;
    const int b   = blockIdx.y;
    // Overlap-clamp final chunk (overlapped p's get identical values -> deterministic)
    const int p0  = min(pc * PP, PLEN - PP);

    // ---- Stage: one global float2 read -> 1 top write + 4 bot phase writes ----
    const float2* in2 = reinterpret_cast<const float2*>(in);
    for (int t = tid; t < NC * NWIN; t += NT) {
        const int c = t / NWIN;
        const int q = t - c * NWIN;                 // 0..29
        float2 v = in2[(size_t)(b * NC + c) * LSEQ + (p0 + q)];
        stop[c][q] = v.x;
        #pragma unroll
        for (int ph = 0; ph < 4; ++ph)
            sbot[c][ph][q + 4 - ph] = v.y;          // m = q+4-ph in [1,33]
    }
    __syncthreads();

    if (tid >= NQUAD) return;

    // ---- Decode quad: slot0 (cA,iA,jA); row-cross at slot k when jA>11 ----
    const int e0   = tid << 2;
    const int cA   = e0 / WW;
    const int remA = e0 - cA * WW;
    const int iA   = remA / W;
    const int jA   = remA - iA * W;
    const int k    = (jA <= W - 4) ? 4 : (W - jA);  // 4 = no cross
    const bool cross = (k < 4);

    int cB = cA, iB = iA;
    if (cross) {
        const int ek   = e0 + k;                    // first element of next (i or c) row
        cB = ek / WW;
        const int remB = ek - cB * WW;
        iB = remB / W;                              // jB == 0 by construction
    }

    const float* topA = &stop[cA][iA];              // advances +1 float per p
    const float* topB = &stop[cB][iB];
    const float* sbase = &sbot[0][0][0];

    // Per-slot float4 base element-offsets (window index x = j0 + lp, lp = 4n+u)
    unsigned offA[4], offB[4];
    #pragma unroll
    for (int u = 0; u < 4; ++u) {
        const unsigned xa4 = (unsigned)(jA + u + 4);         // >= 4
        offA[u] = (unsigned)(cA * 4 + (xa4 & 3u)) * BROW + (xa4 & ~3u);
        const unsigned xb4 = (unsigned)(u - k + 4);          // in [1,7], non-negative
        offB[u] = (unsigned)(cB * 4 + (xb4 & 3u)) * BROW + (xb4 & ~3u);
    }

    float* ob = out + (size_t)(b * PLEN + p0) * CWW + e0;

    #pragma unroll
    for (int n = 0; n < PP / 4; ++n) {
        #pragma unroll
        for (int u = 0; u < 4; ++u) {
            const int lp = 4 * n + u;
            const float  Ta = topA[lp];
            const float4 Ba = *reinterpret_cast<const float4*>(sbase + offA[u] + 4 * n);
            float  Tb = 0.0f;
            float4 Bb = Ba;
            if (cross) {                            // predicated loads (~20% of lanes)
                Tb = topB[lp];
                Bb = *reinterpret_cast<const float4*>(sbase + offB[u] + 4 * n);
            }
            float4 v;                               // per-slot select, k loop-invariant
            v.x = (0 >= k) ? Tb * Bb.x : Ta * Ba.x;
            v.y = (1 >= k) ? Tb * Bb.y : Ta * Ba.y;
            v.z = (2 >= k) ? Tb * Bb.z : Ta * Ba.z;
            v.w = (3 >= k) ? Tb * Bb.w : Ta * Ba.w;
            __stcs(reinterpret_cast<float4*>(ob + (size_t)lp * CWW), v);
        }
    }
}

extern "C" void kernel_launch(void* const* d_in, const int* in_sizes, int n_in,
                              void* d_out, int out_size)
{
    const float* in  = (const float*)d_in[0];
    float*       out = (float*)d_out;
    dim3 grid(NPCHUNK, NB);
    local_interactions_kernel<<<grid, NT>>>(in, out);
}